// round 8
// baseline (speedup 1.0000x reference)
#include <cuda_runtime.h>
#include <cstdint>

#define BB 32
#define NN 4096
#define DU 64
#define DD 128
#define TILES 8
#define CHUNKS 4
#define NBLK (BB*CHUNKS)     // 128 blocks, single wave

// shared-memory layout (float offsets)
#define W1_O 0                       // [64][132]
#define W2_O (W1_O + 64*132)         // [128][132]
#define U_O  (W2_O + 128*132)        // [128][68]
#define Z_O  (U_O  + 128*68)         // [128][132]  (Z1 then Z, aliased)
#define B1_O (Z_O  + 128*132)
#define B2_O (B1_O + 128)
#define SS_O (B2_O + 128)
#define SQF_O (SS_O + 128)
#define SA0_O (SQF_O + 128)
#define SA1_O (SA0_O + 128)
#define SV_O  (SA1_O + 128)          // 256 floats: v0[128], v1[128]
#define SMEM_FLOATS (SV_O + 256)
#define SMEM_BYTES (SMEM_FLOATS * 4) // ~207.9 KB

__device__ float g_partV[NBLK][256];   // per-block a^T G partials (2 heads x 128)
__device__ float g_partS[NBLK][DD];
// precomputed batch-independent tail data
__device__ float g_C0[DD*DD];          // C_0[q][j] = sum_{t<64}  Wv[q][t] Wo[t][j]
__device__ float g_C1[DD*DD];          // C_1[q][j] = sum_{t>=64} Wv[q][t] Wo[t][j]
__device__ float g_a0[DD], g_a1[DD];   // a_h[p] = Wk^T qf per head
__device__ float g_e0[DD], g_e1[DD];   // e_h[j] = sum_{t in h} bv[t] Wo[t][j]
__device__ float g_qbk[2];             // qf_h . bk_h

static __device__ __forceinline__ uint32_t tf32r(float f) {
    uint32_t r; asm("cvt.rna.tf32.f32 %0, %1;" : "=r"(r) : "f"(f)); return r;
}
static __device__ __forceinline__ float tf32f(float f) {
    return __uint_as_float(tf32r(f));
}
// jax.nn.gelu approximate
static __device__ __forceinline__ float gelu_f(float x) {
    float x2 = x * x;
    float y2 = x * fmaf(0.0713548162f, x2, 1.5957691216f);
    float e  = __expf(y2);
    return x - __fdividef(x, e + 1.0f);
}
// m16n8k8 tf32 HMMA, D = A*B + D
static __device__ __forceinline__ void mma8(float* c, const uint32_t* a, const uint32_t* b) {
    asm volatile(
        "mma.sync.aligned.m16n8k8.row.col.f32.tf32.tf32.f32 "
        "{%0,%1,%2,%3},{%4,%5,%6,%7},{%8,%9},{%0,%1,%2,%3};"
        : "+f"(c[0]), "+f"(c[1]), "+f"(c[2]), "+f"(c[3])
        : "r"(a[0]), "r"(a[1]), "r"(a[2]), "r"(a[3]), "r"(b[0]), "r"(b[1]));
}

// ================= precompute: batch-independent tail data =================
__global__ void precompute_kernel(const float* __restrict__ embed,
                                  const float* __restrict__ Wq, const float* __restrict__ bq,
                                  const float* __restrict__ Wk, const float* __restrict__ bk,
                                  const float* __restrict__ Wv, const float* __restrict__ bv,
                                  const float* __restrict__ Wo)
{
    const int j = threadIdx.x;      // 0..127
    const int q = blockIdx.x;       // 0..128
    if (q < DD) {
        __shared__ float wv[DD];
        wv[j] = Wv[q * DD + j];
        __syncthreads();
        float c0 = 0.f, c1 = 0.f;
#pragma unroll 16
        for (int t = 0; t < 64; t++)  c0 = fmaf(wv[t],      Wo[t * DD + j],        c0);
#pragma unroll 16
        for (int t = 0; t < 64; t++)  c1 = fmaf(wv[64 + t], Wo[(64 + t) * DD + j], c1);
        g_C0[q * DD + j] = c0;
        g_C1[q * DD + j] = c1;
    } else {
        // serial chain block: qf -> a_h, e_h, qbk
        __shared__ float qf[DD];
        float acc = bq[j];
#pragma unroll 16
        for (int p = 0; p < DD; p++) acc = fmaf(embed[p], Wq[p * DD + j], acc);
        qf[j] = acc;
        __syncthreads();
        float a0 = 0.f, a1 = 0.f;
#pragma unroll 16
        for (int d = 0; d < 64; d++) {
            a0 = fmaf(qf[d],      Wk[j * DD + d],      a0);
            a1 = fmaf(qf[64 + d], Wk[j * DD + 64 + d], a1);
        }
        g_a0[j] = a0; g_a1[j] = a1;
        float e0 = 0.f, e1 = 0.f;
#pragma unroll 16
        for (int t = 0; t < 64; t++)  e0 = fmaf(bv[t],      Wo[t * DD + j],        e0);
#pragma unroll 16
        for (int t = 0; t < 64; t++)  e1 = fmaf(bv[64 + t], Wo[(64 + t) * DD + j], e1);
        g_e0[j] = e0; g_e1[j] = e1;
        if (j < 2) {
            float s = 0.f;
#pragma unroll 16
            for (int d = 0; d < 64; d++) s = fmaf(qf[j * 64 + d], bk[j * 64 + d], s);
            g_qbk[j] = s;
        }
    }
}

// ================= main fused kernel =================
__global__ void __launch_bounds__(256, 1)
fused_mma_kernel(const float* __restrict__ u,
                 const float* __restrict__ W1, const float* __restrict__ b1,
                 const float* __restrict__ W2, const float* __restrict__ b2,
                 const float* __restrict__ embed,
                 const float* __restrict__ Wq, const float* __restrict__ bq,
                 const float* __restrict__ Wk)
{
    extern __shared__ float sm[];
    const int tid  = threadIdx.x;
    const int w    = tid >> 5;
    const int lane = tid & 31;
    const int lr   = lane >> 2;      // fragment row group 0..7
    const int lc   = lane & 3;       // fragment k group 0..3
    const int mb   = (w >> 1) * 32;  // warp row base
    const int nb   = (w & 1) * 64;   // warp col base

    // ---- stage weights as tf32 ----
    for (int i = tid; i < 64 * 128; i += 256) {
        int k = i >> 7, n = i & 127;
        sm[W1_O + k * 132 + n] = tf32f(W1[i]);
    }
    for (int i = tid; i < 128 * 128; i += 256) {
        int k = i >> 7, n = i & 127;
        sm[W2_O + k * 132 + n] = tf32f(W2[i]);
    }
    if (tid < 128) {
        sm[B1_O + tid] = b1[tid]; sm[B2_O + tid] = b2[tid];
        sm[SS_O + tid] = 0.f;
        sm[SV_O + tid] = 0.f; sm[SV_O + 128 + tid] = 0.f;
        // qf[t] = embed @ Wq + bq (identical across blocks; L2-broadcast reads)
        float acc = bq[tid];
#pragma unroll 8
        for (int p = 0; p < DD; p++) acc = fmaf(embed[p], Wq[p * DD + tid], acc);
        sm[SQF_O + tid] = acc;
    }

    float g[2][8][4];     // Gram accumulators
#pragma unroll
    for (int mt = 0; mt < 2; mt++)
#pragma unroll
        for (int nt = 0; nt < 8; nt++)
#pragma unroll
            for (int i = 0; i < 4; i++) g[mt][nt][i] = 0.f;
    float sacc[16];
#pragma unroll
    for (int i = 0; i < 16; i++) sacc[i] = 0.f;

    const int bid = blockIdx.x;
    const float* ub = u + ((size_t)(bid >> 2) * NN + (size_t)(bid & 3) * 1024) * DU;

    __syncthreads();

    // a_h[p] = sum_d qf[h*64+d] * Wk[p][h*64+d]
    if (tid < 128) {
        float a0 = 0.f, a1 = 0.f;
#pragma unroll 8
        for (int d = 0; d < 64; d++) {
            a0 = fmaf(sm[SQF_O + d],      Wk[tid * DD + d],      a0);
            a1 = fmaf(sm[SQF_O + 64 + d], Wk[tid * DD + 64 + d], a1);
        }
        sm[SA0_O + tid] = a0; sm[SA1_O + tid] = a1;
    }

    float b1r[16], b2r[16];
#pragma unroll
    for (int nt = 0; nt < 8; nt++) {
        int col = nb + nt * 8 + 2 * lc;
        b1r[nt * 2] = sm[B1_O + col]; b1r[nt * 2 + 1] = sm[B1_O + col + 1];
        b2r[nt * 2] = sm[B2_O + col]; b2r[nt * 2 + 1] = sm[B2_O + col + 1];
    }

    // prefetch tile 0 into registers
    float4 pref[8];
    {
        const float4* uv = (const float4*)ub;
#pragma unroll
        for (int i = 0; i < 8; i++) pref[i] = uv[i * 256 + tid];
    }

    for (int tt = 0; tt < TILES; tt++) {
        // ---- store prefetched U tile (tf32, pitch 68), then prefetch next ----
#pragma unroll
        for (int i = 0; i < 8; i++) {
            int idx = i * 256 + tid;
            int tok = idx >> 4, kq = idx & 15;
            float4 f = pref[i];
            *(float4*)&sm[U_O + tok * 68 + kq * 4] =
                make_float4(tf32f(f.x), tf32f(f.y), tf32f(f.z), tf32f(f.w));
        }
        if (tt + 1 < TILES) {
            const float4* uv = (const float4*)(ub + (size_t)(tt + 1) * 128 * DU);
#pragma unroll
            for (int i = 0; i < 8; i++) pref[i] = uv[i * 256 + tid];
        }
        __syncthreads();

        float c[2][8][4];

        // ======== MLP1: C = U @ W1  (K=64) ========
#pragma unroll
        for (int mt = 0; mt < 2; mt++)
#pragma unroll
            for (int nt = 0; nt < 8; nt++)
#pragma unroll
                for (int i = 0; i < 4; i++) c[mt][nt][i] = 0.f;
        {
            const float* As = &sm[U_O + (mb + lr) * 68 + lc];
            const float* Bs = &sm[W1_O + lc * 132 + nb + lr];
#pragma unroll 4
            for (int kt = 0; kt < 8; kt++) {
                uint32_t a[2][4], bf[8][2];
#pragma unroll
                for (int mt = 0; mt < 2; mt++) {
                    const float* p = As + mt * 16 * 68 + kt * 8;
                    a[mt][0] = __float_as_uint(p[0]);
                    a[mt][1] = __float_as_uint(p[8 * 68]);
                    a[mt][2] = __float_as_uint(p[4]);
                    a[mt][3] = __float_as_uint(p[8 * 68 + 4]);
                }
#pragma unroll
                for (int nt = 0; nt < 8; nt++) {
                    const float* p = Bs + kt * 8 * 132 + nt * 8;
                    bf[nt][0] = __float_as_uint(p[0]);
                    bf[nt][1] = __float_as_uint(p[4 * 132]);
                }
#pragma unroll
                for (int mt = 0; mt < 2; mt++)
#pragma unroll
                    for (int nt = 0; nt < 8; nt++) mma8(c[mt][nt], a[mt], bf[nt]);
            }
        }
        __syncthreads();

        // epilogue 1: Z1 = gelu(C + b1)
#pragma unroll
        for (int mt = 0; mt < 2; mt++)
#pragma unroll
            for (int nt = 0; nt < 8; nt++) {
                int row = mb + mt * 16 + lr;
                int col = nb + nt * 8 + 2 * lc;
                float z0 = gelu_f(c[mt][nt][0] + b1r[nt * 2]);
                float z1 = gelu_f(c[mt][nt][1] + b1r[nt * 2 + 1]);
                float z2 = gelu_f(c[mt][nt][2] + b1r[nt * 2]);
                float z3 = gelu_f(c[mt][nt][3] + b1r[nt * 2 + 1]);
                *(float2*)&sm[Z_O + row * 132 + col]       = make_float2(tf32f(z0), tf32f(z1));
                *(float2*)&sm[Z_O + (row + 8) * 132 + col] = make_float2(tf32f(z2), tf32f(z3));
            }
        __syncthreads();

        // ======== MLP2: C = Z1 @ W2  (K=128) ========
#pragma unroll
        for (int mt = 0; mt < 2; mt++)
#pragma unroll
            for (int nt = 0; nt < 8; nt++)
#pragma unroll
                for (int i = 0; i < 4; i++) c[mt][nt][i] = 0.f;
        {
            const float* As = &sm[Z_O + (mb + lr) * 132 + lc];
            const float* Bs = &sm[W2_O + lc * 132 + nb + lr];
#pragma unroll 4
            for (int kt = 0; kt < 16; kt++) {
                uint32_t a[2][4], bf[8][2];
#pragma unroll
                for (int mt = 0; mt < 2; mt++) {
                    const float* p = As + mt * 16 * 132 + kt * 8;
                    a[mt][0] = __float_as_uint(p[0]);
                    a[mt][1] = __float_as_uint(p[8 * 132]);
                    a[mt][2] = __float_as_uint(p[4]);
                    a[mt][3] = __float_as_uint(p[8 * 132 + 4]);
                }
#pragma unroll
                for (int nt = 0; nt < 8; nt++) {
                    const float* p = Bs + kt * 8 * 132 + nt * 8;
                    bf[nt][0] = __float_as_uint(p[0]);
                    bf[nt][1] = __float_as_uint(p[4 * 132]);
                }
#pragma unroll
                for (int mt = 0; mt < 2; mt++)
#pragma unroll
                    for (int nt = 0; nt < 8; nt++) mma8(c[mt][nt], a[mt], bf[nt]);
            }
        }
        __syncthreads();

        // epilogue 2: Z = gelu(C + b2); S += columns
#pragma unroll
        for (int mt = 0; mt < 2; mt++)
#pragma unroll
            for (int nt = 0; nt < 8; nt++) {
                int row = mb + mt * 16 + lr;
                int col = nb + nt * 8 + 2 * lc;
                float z0 = gelu_f(c[mt][nt][0] + b2r[nt * 2]);
                float z1 = gelu_f(c[mt][nt][1] + b2r[nt * 2 + 1]);
                float z2 = gelu_f(c[mt][nt][2] + b2r[nt * 2]);
                float z3 = gelu_f(c[mt][nt][3] + b2r[nt * 2 + 1]);
                sacc[nt * 2]     += z0 + z2;
                sacc[nt * 2 + 1] += z1 + z3;
                *(float2*)&sm[Z_O + row * 132 + col]       = make_float2(tf32f(z0), tf32f(z1));
                *(float2*)&sm[Z_O + (row + 8) * 132 + col] = make_float2(tf32f(z2), tf32f(z3));
            }
        __syncthreads();

        // ======== Gram: G += Z^T @ Z ========
        {
#pragma unroll 4
            for (int kt = 0; kt < 16; kt++) {
                uint32_t a[2][4], bf[8][2];
                const float* At = &sm[Z_O + (kt * 8 + lc) * 132 + mb + lr];
#pragma unroll
                for (int mt = 0; mt < 2; mt++) {
                    const float* p = At + mt * 16;
                    a[mt][0] = __float_as_uint(p[0]);
                    a[mt][1] = __float_as_uint(p[8]);
                    a[mt][2] = __float_as_uint(p[4 * 132]);
                    a[mt][3] = __float_as_uint(p[4 * 132 + 8]);
                }
                const float* Bt = &sm[Z_O + (kt * 8 + lc) * 132 + nb + lr];
#pragma unroll
                for (int nt = 0; nt < 8; nt++) {
                    const float* p = Bt + nt * 8;
                    bf[nt][0] = __float_as_uint(p[0]);
                    bf[nt][1] = __float_as_uint(p[4 * 132]);
                }
#pragma unroll
                for (int mt = 0; mt < 2; mt++)
#pragma unroll
                    for (int nt = 0; nt < 8; nt++) mma8(g[mt][nt], a[mt], bf[nt]);
            }
        }
        __syncthreads();
    }

    // ---- contract G with a_h in-register: v_h[col] = sum_rows a_h[row]*G[row][col] ----
    {
        float ar0[2][2], ar1[2][2];
#pragma unroll
        for (int mt = 0; mt < 2; mt++) {
            int row = mb + mt * 16 + lr;
            ar0[mt][0] = sm[SA0_O + row];     ar0[mt][1] = sm[SA0_O + row + 8];
            ar1[mt][0] = sm[SA1_O + row];     ar1[mt][1] = sm[SA1_O + row + 8];
        }
        float v0[16], v1[16];
#pragma unroll
        for (int nt = 0; nt < 8; nt++)
#pragma unroll
            for (int j = 0; j < 2; j++) {
                float s0 = 0.f, s1 = 0.f;
#pragma unroll
                for (int mt = 0; mt < 2; mt++) {
                    s0 = fmaf(ar0[mt][0], g[mt][nt][j],     s0);
                    s0 = fmaf(ar0[mt][1], g[mt][nt][2 + j], s0);
                    s1 = fmaf(ar1[mt][0], g[mt][nt][j],     s1);
                    s1 = fmaf(ar1[mt][1], g[mt][nt][2 + j], s1);
                }
                v0[nt * 2 + j] = s0; v1[nt * 2 + j] = s1;
            }
#pragma unroll
        for (int i = 0; i < 16; i++) {
            v0[i] += __shfl_down_sync(0xFFFFFFFFu, v0[i], 16);
            v0[i] += __shfl_down_sync(0xFFFFFFFFu, v0[i], 8);
            v0[i] += __shfl_down_sync(0xFFFFFFFFu, v0[i], 4);
            v1[i] += __shfl_down_sync(0xFFFFFFFFu, v1[i], 16);
            v1[i] += __shfl_down_sync(0xFFFFFFFFu, v1[i], 8);
            v1[i] += __shfl_down_sync(0xFFFFFFFFu, v1[i], 4);
        }
        if (lr == 0) {
#pragma unroll
            for (int i = 0; i < 16; i++) {
                int col = nb + (i >> 1) * 8 + 2 * lc + (i & 1);
                atomicAdd(&sm[SV_O + col],       v0[i]);
                atomicAdd(&sm[SV_O + 128 + col], v1[i]);
            }
        }
    }

    // ---- reduce S ----
#pragma unroll
    for (int i = 0; i < 16; i++) {
        float v = sacc[i];
        v += __shfl_down_sync(0xFFFFFFFFu, v, 16);
        v += __shfl_down_sync(0xFFFFFFFFu, v, 8);
        v += __shfl_down_sync(0xFFFFFFFFu, v, 4);
        if (lr == 0) atomicAdd(&sm[SS_O + nb + (i >> 1) * 8 + 2 * lc + (i & 1)], v);
    }
    __syncthreads();
    if (tid < 128) g_partS[bid][tid] = sm[SS_O + tid];
    g_partV[bid][tid] = sm[SV_O + tid];
}

// ================= tail: single-phase final combine =================
__global__ void tail_kernel(const float* __restrict__ bo, float* __restrict__ out)
{
    __shared__ float ss[DD], w0[DD], w1[DD], sa0[DD], sa1[DD];
    const int t = threadIdx.x;   // 0..127
    const int b = blockIdx.x;    // 0..31

    float s  = g_partS[b*4][t] + g_partS[b*4+1][t] + g_partS[b*4+2][t] + g_partS[b*4+3][t];
    float v0 = g_partV[b*4][t] + g_partV[b*4+1][t] + g_partV[b*4+2][t] + g_partV[b*4+3][t];
    float v1 = g_partV[b*4][128+t] + g_partV[b*4+1][128+t] + g_partV[b*4+2][128+t] + g_partV[b*4+3][128+t];
    const float qbk0 = g_qbk[0], qbk1 = g_qbk[1];

    ss[t]  = s;
    w0[t]  = v0 + qbk0 * s;
    w1[t]  = v1 + qbk1 * s;
    sa0[t] = g_a0[t];
    sa1[t] = g_a1[t];
    __syncthreads();

    // asd_h = a_h . s  (redundant per-thread, smem broadcast)
    float asd0 = 0.f, asd1 = 0.f;
#pragma unroll 16
    for (int q = 0; q < DD; q++) {
        asd0 = fmaf(sa0[q], ss[q], asd0);
        asd1 = fmaf(sa1[q], ss[q], asd1);
    }

    float acc = 0.f;
#pragma unroll 16
    for (int q = 0; q < DD; q++) {
        acc = fmaf(w0[q], g_C0[q * DD + t], acc);
        acc = fmaf(w1[q], g_C1[q * DD + t], acc);
    }
    acc += (asd0 + (float)NN * qbk0) * g_e0[t];
    acc += (asd1 + (float)NN * qbk1) * g_e1[t];

    out[b * DD + t] = bo[t] + acc * (1.0f / (float)NN);
}

// ================= launch =================
extern "C" void kernel_launch(void* const* d_in, const int* in_sizes, int n_in,
                              void* d_out, int out_size)
{
    const float* u     = (const float*)d_in[0];
    const float* W1    = (const float*)d_in[2];
    const float* b1    = (const float*)d_in[3];
    const float* W2    = (const float*)d_in[4];
    const float* b2    = (const float*)d_in[5];
    const float* embed = (const float*)d_in[6];
    const float* Wq    = (const float*)d_in[7];
    const float* bq    = (const float*)d_in[8];
    const float* Wk    = (const float*)d_in[9];
    const float* bk    = (const float*)d_in[10];
    const float* Wv    = (const float*)d_in[11];
    const float* bv    = (const float*)d_in[12];
    const float* Wo    = (const float*)d_in[13];
    const float* bo    = (const float*)d_in[14];
    float* out = (float*)d_out;

    cudaFuncSetAttribute(fused_mma_kernel,
                         cudaFuncAttributeMaxDynamicSharedMemorySize, SMEM_BYTES);

    precompute_kernel<<<DD + 1, DD>>>(embed, Wq, bq, Wk, bk, Wv, bv, Wo);
    fused_mma_kernel<<<NBLK, 256, SMEM_BYTES>>>(u, W1, b1, W2, b2, embed, Wq, bq, Wk);
    tail_kernel<<<BB, DD>>>(bo, out);
}